// round 11
// baseline (speedup 1.0000x reference)
#include <cuda_runtime.h>
#include <cstdint>
#include <cstddef>

#define TOKS 4096
#define EMB  1024
#define HID  4096
#define NE   8
#define CAP  4096

#define TM 128           // CTA tile M
#define TN 256           // CTA tile N
#define TK 32            // k floats per stage
#define LDSR 36          // padded smem row stride (floats)
#define NSTAGE 3

// ---------------- scratch (device globals; no allocations allowed) ----------------
__device__ int   g_cnt[NE];
__device__ float g_sumprob[NE];
__device__ int   g_tok[NE * CAP];
__device__ int   g_map[TOKS * 2];
__device__ float g_gatew[TOKS * 2];
__device__ float g_xa[(size_t)NE * CAP * EMB];   // gathered activations, tf32 bits
__device__ float g_s1[(size_t)NE * CAP * HID];   // X@W1^T fp32, then h (tf32 bits, in-place)
__device__ float g_y [(size_t)NE * CAP * EMB];   // H@W3^T fp32

// ---------------- helpers ----------------
__device__ __forceinline__ uint32_t f2tf(float f) {
    uint32_t u;
    asm("cvt.rna.tf32.f32 %0, %1;" : "=r"(u) : "f"(f));
    return u;
}
__device__ __forceinline__ void cpa16(void* s, const void* g) {
    uint32_t sa = (uint32_t)__cvta_generic_to_shared(s);
    asm volatile("cp.async.cg.shared.global [%0], [%1], 16;\n" :: "r"(sa), "l"(g));
}
__device__ __forceinline__ void mma_tf32(float* c, const uint32_t* a, const uint32_t* b) {
    asm volatile(
        "mma.sync.aligned.m16n8k8.row.col.f32.tf32.tf32.f32 "
        "{%0,%1,%2,%3}, {%4,%5,%6,%7}, {%8,%9}, {%0,%1,%2,%3};\n"
        : "+f"(c[0]), "+f"(c[1]), "+f"(c[2]), "+f"(c[3])
        : "r"(a[0]), "r"(a[1]), "r"(a[2]), "r"(a[3]), "r"(b[0]), "r"(b[1]));
}
__device__ __forceinline__ float silu_mul(float a, float b) {
    return (a / (1.f + expf(-a))) * b;
}

// ---------------- small kernels ----------------
__global__ void init_kernel() {
    int i = threadIdx.x;
    if (i < NE) { g_cnt[i] = 0; g_sumprob[i] = 0.f; }
}

// one warp per token: scores, top-2, softmax gates, slot assignment, aux accumulation
__global__ void router_kernel(const float* __restrict__ x, const float* __restrict__ gw) {
    __shared__ float s_ps[NE];
    int tid = threadIdx.x, lane = tid & 31, wid = tid >> 5;
    if (tid < NE) s_ps[tid] = 0.f;
    __syncthreads();

    int t = blockIdx.x * 8 + wid;
    float acc[NE];
#pragma unroll
    for (int e = 0; e < NE; e++) acc[e] = 0.f;
    const float* xr = x + (size_t)t * EMB;
    for (int i = lane; i < EMB; i += 32) {
        float xi = xr[i];
#pragma unroll
        for (int e = 0; e < NE; e++) acc[e] += xi * gw[e * EMB + i];
    }
#pragma unroll
    for (int e = 0; e < NE; e++) {
#pragma unroll
        for (int o = 16; o > 0; o >>= 1) acc[e] += __shfl_xor_sync(0xffffffffu, acc[e], o);
    }
    if (lane == 0) {
        float m = acc[0];
#pragma unroll
        for (int e = 1; e < NE; e++) m = fmaxf(m, acc[e]);
        float pe[NE], se = 0.f;
#pragma unroll
        for (int e = 0; e < NE; e++) { pe[e] = expf(acc[e] - m); se += pe[e]; }
        float inv = 1.f / se;
#pragma unroll
        for (int e = 0; e < NE; e++) atomicAdd(&s_ps[e], pe[e] * inv);

        // top-2 (ties: lowest index first, matching jax top_k)
        int i1 = 0;
#pragma unroll
        for (int e = 1; e < NE; e++) if (acc[e] > acc[i1]) i1 = e;
        int i2 = (i1 == 0) ? 1 : 0;
#pragma unroll
        for (int e = 0; e < NE; e++) if (e != i1 && acc[e] > acc[i2]) i2 = e;

        float p1 = 1.f / (1.f + expf(acc[i2] - acc[i1]));
        float p2 = 1.f - p1;
        int s1 = atomicAdd(&g_cnt[i1], 1);
        int s2 = atomicAdd(&g_cnt[i2], 1);
        g_tok[i1 * CAP + s1] = t;
        g_tok[i2 * CAP + s2] = t;
        g_map[t * 2 + 0] = i1 * CAP + s1;
        g_map[t * 2 + 1] = i2 * CAP + s2;
        g_gatew[t * 2 + 0] = p1;
        g_gatew[t * 2 + 1] = p2;
    }
    __syncthreads();
    if (tid < NE) atomicAdd(&g_sumprob[tid], s_ps[tid]);
}

// one warp per (expert, slot): copy token row into expert-contiguous scratch (tf32 bits)
__global__ void gather_kernel(const float* __restrict__ x) {
    int w = (blockIdx.x * blockDim.x + threadIdx.x) >> 5;
    int lane = threadIdx.x & 31;
    int e = w >> 12, s = w & (CAP - 1);
    if (s >= g_cnt[e]) return;
    int t = g_tok[w];
    const float4* src = (const float4*)(x + (size_t)t * EMB);
    float4* dst = (float4*)(g_xa + (size_t)w * EMB);
#pragma unroll 4
    for (int i = lane; i < EMB / 4; i += 32) {
        float4 v = src[i];
        float4 o;
        o.x = __uint_as_float(f2tf(v.x));
        o.y = __uint_as_float(f2tf(v.y));
        o.z = __uint_as_float(f2tf(v.z));
        o.w = __uint_as_float(f2tf(v.w));
        dst[i] = o;
    }
}

// ---------------- grouped GEMM: 128x256x32 tiles, 8 warps (2x4), warp tile 64x64 ----
// C[m][n] = sum_k A[m][k] * W[n][k]  (tf32 mma.sync, 3-stage cp.async)
// MODE 0: A=g_xa (K=EMB), W=w1, epilogue: raw fp32 -> g_s1
// MODE 1: A=g_xa (K=EMB), W=w2, epilogue: h=silu(s1+b1)*(acc+b2) -> g_s1 (tf32 bits)
// MODE 2: A=g_s1 (K=HID), W=w3, epilogue: raw fp32 -> g_y
template <int MODE>
__global__ __launch_bounds__(256, 1) void gemm_kernel(const float* __restrict__ W,
                                                      const float* __restrict__ bias1,
                                                      const float* __restrict__ bias2) {
    constexpr int K = (MODE == 2) ? HID : EMB;
    constexpr int N = (MODE == 2) ? EMB : HID;
    constexpr int NKT = K / TK;
    constexpr int STAGEF = (TM + TN) * LDSR;   // floats per stage

    int e = blockIdx.z;
    int cnt = g_cnt[e];
    int mt = blockIdx.y;
    if (mt * TM >= cnt) return;

    const float* A = (MODE == 2) ? g_s1 : g_xa;
    float* C = (MODE == 0) ? g_s1 : (MODE == 1) ? g_s1 : g_y;  // MODE1 writes g_s1 (fused)

    const float* Ae = A + (size_t)e * CAP * K + (size_t)mt * TM * K;
    const float* Be = W + (size_t)e * N * K + (size_t)blockIdx.x * TN * K;
    int n0 = blockIdx.x * TN;

    extern __shared__ float smem[];

    int tid = threadIdx.x, lane = tid & 31, wid = tid >> 5;
    int wm = wid & 1, wn = wid >> 1;   // 2(M) x 4(N) warps -> warp tile 64x64

    float acc[4][8][4];
#pragma unroll
    for (int m = 0; m < 4; m++)
#pragma unroll
        for (int n = 0; n < 8; n++)
#pragma unroll
            for (int i = 0; i < 4; i++) acc[m][n][i] = 0.f;

    auto load_stage = [&](int s, int kt) {
        float* Ab = smem + s * STAGEF;
        float* Bb = Ab + TM * LDSR;
        const float* Ag = Ae + kt * TK;
        const float* Bg = Be + kt * TK;
#pragma unroll
        for (int i = 0; i < 4; i++) {           // A: 128 rows x 8 chunks of 16B
            int idx = tid + i * 256;
            int r = idx >> 3, c4 = (idx & 7) * 4;
            cpa16(&Ab[r * LDSR + c4], Ag + (size_t)r * K + c4);
        }
#pragma unroll
        for (int i = 0; i < 8; i++) {           // B: 256 rows x 8 chunks of 16B
            int idx = tid + i * 256;
            int r = idx >> 3, c4 = (idx & 7) * 4;
            cpa16(&Bb[r * LDSR + c4], Bg + (size_t)r * K + c4);
        }
        asm volatile("cp.async.commit_group;\n");
    };

    load_stage(0, 0);
    load_stage(1, 1);
    load_stage(2, 2);

    int buf = 0;
    for (int kt = 0; kt < NKT; kt++) {
        asm volatile("cp.async.wait_group 2;\n" ::: "memory");
        __syncthreads();

        const float* Asb = smem + buf * STAGEF;
        const float* Bsb = Asb + TM * LDSR;
#pragma unroll
        for (int ks = 0; ks < 4; ks++) {
            uint32_t af[4][4], bf[8][2];
            int kc = ks * 8 + (lane & 3);
#pragma unroll
            for (int m = 0; m < 4; m++) {
                int r = wm * 64 + m * 16 + (lane >> 2);
                af[m][0] = __float_as_uint(Asb[r * LDSR + kc]);       // pre-converted tf32
                af[m][1] = __float_as_uint(Asb[(r + 8) * LDSR + kc]);
                af[m][2] = __float_as_uint(Asb[r * LDSR + kc + 4]);
                af[m][3] = __float_as_uint(Asb[(r + 8) * LDSR + kc + 4]);
            }
#pragma unroll
            for (int n = 0; n < 8; n++) {
                int cn = wn * 64 + n * 8 + (lane >> 2);
                bf[n][0] = f2tf(Bsb[cn * LDSR + kc]);
                bf[n][1] = f2tf(Bsb[cn * LDSR + kc + 4]);
            }
#pragma unroll
            for (int m = 0; m < 4; m++)
#pragma unroll
                for (int n = 0; n < 8; n++) mma_tf32(acc[m][n], af[m], bf[n]);
        }
        __syncthreads();   // all warps done reading this stage before refill

        if (kt + NSTAGE < NKT) load_stage(buf, kt + NSTAGE);
        else asm volatile("cp.async.commit_group;\n");   // empty group keeps count aligned

        buf = (buf == NSTAGE - 1) ? 0 : buf + 1;
    }

    // ---- epilogue ----
#pragma unroll
    for (int m = 0; m < 4; m++) {
        int rb = wm * 64 + m * 16 + (lane >> 2);
#pragma unroll
        for (int half = 0; half < 2; half++) {
            int r = rb + half * 8;
            size_t grow = (size_t)e * CAP + (size_t)mt * TM + r;
            if (MODE == 1) {
                float* s1row = g_s1 + grow * (size_t)HID;
                const float* b1p = bias1 + (size_t)e * HID;
                const float* b2p = bias2 + (size_t)e * HID;
#pragma unroll
                for (int n = 0; n < 8; n++) {
                    int col = n0 + wn * 64 + n * 8 + (lane & 3) * 2;
                    float2 s1v = *(const float2*)(s1row + col);
                    float2 b1v = *(const float2*)(b1p + col);
                    float2 b2v = *(const float2*)(b2p + col);
                    float h0 = silu_mul(s1v.x + b1v.x, acc[m][n][2 * half + 0] + b2v.x);
                    float h1 = silu_mul(s1v.y + b1v.y, acc[m][n][2 * half + 1] + b2v.y);
                    float2 o;
                    o.x = __uint_as_float(f2tf(h0));
                    o.y = __uint_as_float(f2tf(h1));
                    *(float2*)(s1row + col) = o;
                }
            } else {
                float* Crow = C + grow * (size_t)N;
#pragma unroll
                for (int n = 0; n < 8; n++) {
                    int col = n0 + wn * 64 + n * 8 + (lane & 3) * 2;
                    float2 o = make_float2(acc[m][n][2 * half + 0], acc[m][n][2 * half + 1]);
                    *(float2*)(Crow + col) = o;
                }
            }
        }
    }
}

// out[t] = sum_k gate_k * (Y[slot_k] + b3[e_k])
__global__ void combine_kernel(float* __restrict__ out, const float* __restrict__ b3) {
    int w = (blockIdx.x * blockDim.x + threadIdx.x) >> 5;
    int lane = threadIdx.x & 31;
    if (w >= TOKS) return;
    int m0 = g_map[2 * w], m1 = g_map[2 * w + 1];
    float p0 = g_gatew[2 * w], p1 = g_gatew[2 * w + 1];
    int e0 = m0 >> 12, e1 = m1 >> 12;
    const float4* y0 = (const float4*)(g_y + (size_t)m0 * EMB);
    const float4* y1 = (const float4*)(g_y + (size_t)m1 * EMB);
    const float4* bb0 = (const float4*)(b3 + (size_t)e0 * EMB);
    const float4* bb1 = (const float4*)(b3 + (size_t)e1 * EMB);
    float4* o = (float4*)(out + (size_t)w * EMB);
    for (int i = lane; i < EMB / 4; i += 32) {
        float4 a = y0[i], b = y1[i], c = bb0[i], d = bb1[i];
        float4 r;
        r.x = p0 * (a.x + c.x) + p1 * (b.x + d.x);
        r.y = p0 * (a.y + c.y) + p1 * (b.y + d.y);
        r.z = p0 * (a.z + c.z) + p1 * (b.z + d.z);
        r.w = p0 * (a.w + c.w) + p1 * (b.w + d.w);
        o[i] = r;
    }
}

__global__ void aux_kernel(float* __restrict__ out, int out_size) {
    if (threadIdx.x == 0 && blockIdx.x == 0 && out_size > TOKS * EMB) {
        float a = 0.f;
        for (int e = 0; e < NE; e++)
            a += ((float)g_cnt[e] / (float)TOKS) * (g_sumprob[e] / (float)TOKS);
        out[TOKS * EMB] = (float)NE * a;
    }
}

// ---------------- launcher ----------------
extern "C" void kernel_launch(void* const* d_in, const int* in_sizes, int n_in,
                              void* d_out, int out_size) {
    const float* x  = (const float*)d_in[0];
    const float* gw = (const float*)d_in[1];
    const float* w1 = (const float*)d_in[2];
    const float* b1 = (const float*)d_in[3];
    const float* w2 = (const float*)d_in[4];
    const float* b2 = (const float*)d_in[5];
    const float* w3 = (const float*)d_in[6];
    const float* b3 = (const float*)d_in[7];
    float* out = (float*)d_out;

    const int SMEM_BYTES = NSTAGE * (TM + TN) * LDSR * 4;   // 165888

    cudaFuncSetAttribute(gemm_kernel<0>, cudaFuncAttributeMaxDynamicSharedMemorySize, SMEM_BYTES);
    cudaFuncSetAttribute(gemm_kernel<1>, cudaFuncAttributeMaxDynamicSharedMemorySize, SMEM_BYTES);
    cudaFuncSetAttribute(gemm_kernel<2>, cudaFuncAttributeMaxDynamicSharedMemorySize, SMEM_BYTES);

    init_kernel<<<1, 32>>>();
    router_kernel<<<TOKS / 8, 256>>>(x, gw);
    gather_kernel<<<NE * CAP / 8, 256>>>(x);
    gemm_kernel<0><<<dim3(HID / TN, CAP / TM, NE), 256, SMEM_BYTES>>>(w1, nullptr, nullptr);
    gemm_kernel<1><<<dim3(HID / TN, CAP / TM, NE), 256, SMEM_BYTES>>>(w2, b1, b2);
    gemm_kernel<2><<<dim3(EMB / TN, CAP / TM, NE), 256, SMEM_BYTES>>>(w3, nullptr, nullptr);
    combine_kernel<<<TOKS / 8, 256>>>(out, b3);
    aux_kernel<<<1, 32>>>(out, out_size);
}

// round 14
// speedup vs baseline: 1.3532x; 1.3532x over previous
#include <cuda_runtime.h>
#include <cstdint>
#include <cstddef>

#define TOKS 4096
#define EMB  1024
#define HID  4096
#define NE   8
#define CAP  4096
#define LDSR 36          // padded smem row stride (floats)

// ---------------- scratch (device globals; no allocations allowed) ----------------
__device__ int   g_cnt[NE];
__device__ float g_sumprob[NE];
__device__ int   g_tok[NE * CAP];
__device__ float g_slotgate[NE * CAP];           // per-slot gate weight
__device__ float g_xa[(size_t)NE * CAP * EMB];   // gathered activations, tf32 bits
__device__ float g_s1[(size_t)NE * CAP * HID];   // h (tf32 bits)

// ---------------- helpers ----------------
__device__ __forceinline__ uint32_t f2tf(float f) {
    uint32_t u;
    asm("cvt.rna.tf32.f32 %0, %1;" : "=r"(u) : "f"(f));
    return u;
}
__device__ __forceinline__ void cpa16(void* s, const void* g) {
    uint32_t sa = (uint32_t)__cvta_generic_to_shared(s);
    asm volatile("cp.async.cg.shared.global [%0], [%1], 16;\n" :: "r"(sa), "l"(g));
}
__device__ __forceinline__ void mma_tf32(float* c, const uint32_t* a, const uint32_t* b) {
    asm volatile(
        "mma.sync.aligned.m16n8k8.row.col.f32.tf32.tf32.f32 "
        "{%0,%1,%2,%3}, {%4,%5,%6,%7}, {%8,%9}, {%0,%1,%2,%3};\n"
        : "+f"(c[0]), "+f"(c[1]), "+f"(c[2]), "+f"(c[3])
        : "r"(a[0]), "r"(a[1]), "r"(a[2]), "r"(a[3]), "r"(b[0]), "r"(b[1]));
}
__device__ __forceinline__ float silu_mul(float a, float b) {
    return (a / (1.f + expf(-a))) * b;
}

// ---------------- small kernels ----------------
__global__ void init_kernel() {
    int i = threadIdx.x;
    if (i < NE) { g_cnt[i] = 0; g_sumprob[i] = 0.f; }
}

__global__ void zero_out_kernel(float4* __restrict__ out) {
    int i = blockIdx.x * blockDim.x + threadIdx.x;
    int stride = gridDim.x * blockDim.x;
    const int n4 = TOKS * EMB / 4;
    for (; i < n4; i += stride) out[i] = make_float4(0.f, 0.f, 0.f, 0.f);
}

// one warp per token: scores, top-2, softmax gates, slot assignment, aux accumulation
__global__ void router_kernel(const float* __restrict__ x, const float* __restrict__ gw) {
    __shared__ float s_ps[NE];
    int tid = threadIdx.x, lane = tid & 31, wid = tid >> 5;
    if (tid < NE) s_ps[tid] = 0.f;
    __syncthreads();

    int t = blockIdx.x * 8 + wid;
    float acc[NE];
#pragma unroll
    for (int e = 0; e < NE; e++) acc[e] = 0.f;
    const float* xr = x + (size_t)t * EMB;
    for (int i = lane; i < EMB; i += 32) {
        float xi = xr[i];
#pragma unroll
        for (int e = 0; e < NE; e++) acc[e] += xi * gw[e * EMB + i];
    }
#pragma unroll
    for (int e = 0; e < NE; e++) {
#pragma unroll
        for (int o = 16; o > 0; o >>= 1) acc[e] += __shfl_xor_sync(0xffffffffu, acc[e], o);
    }
    if (lane == 0) {
        float m = acc[0];
#pragma unroll
        for (int e = 1; e < NE; e++) m = fmaxf(m, acc[e]);
        float pe[NE], se = 0.f;
#pragma unroll
        for (int e = 0; e < NE; e++) { pe[e] = expf(acc[e] - m); se += pe[e]; }
        float inv = 1.f / se;
#pragma unroll
        for (int e = 0; e < NE; e++) atomicAdd(&s_ps[e], pe[e] * inv);

        // top-2 (ties: lowest index first, matching jax top_k)
        int i1 = 0;
#pragma unroll
        for (int e = 1; e < NE; e++) if (acc[e] > acc[i1]) i1 = e;
        int i2 = (i1 == 0) ? 1 : 0;
#pragma unroll
        for (int e = 0; e < NE; e++) if (e != i1 && acc[e] > acc[i2]) i2 = e;

        float p1 = 1.f / (1.f + expf(acc[i2] - acc[i1]));
        float p2 = 1.f - p1;
        int s1 = atomicAdd(&g_cnt[i1], 1);
        int s2 = atomicAdd(&g_cnt[i2], 1);
        g_tok[i1 * CAP + s1] = t;
        g_tok[i2 * CAP + s2] = t;
        g_slotgate[i1 * CAP + s1] = p1;
        g_slotgate[i2 * CAP + s2] = p2;
    }
    __syncthreads();
    if (tid < NE) atomicAdd(&g_sumprob[tid], s_ps[tid]);
}

// one warp per (expert, slot): copy token row into expert-contiguous scratch (tf32 bits)
__global__ void gather_kernel(const float* __restrict__ x) {
    int w = (blockIdx.x * blockDim.x + threadIdx.x) >> 5;
    int lane = threadIdx.x & 31;
    int e = w >> 12, s = w & (CAP - 1);
    if (s >= g_cnt[e]) return;
    int t = g_tok[w];
    const float4* src = (const float4*)(x + (size_t)t * EMB);
    float4* dst = (float4*)(g_xa + (size_t)w * EMB);
#pragma unroll 4
    for (int i = lane; i < EMB / 4; i += 32) {
        float4 v = src[i];
        float4 o;
        o.x = __uint_as_float(f2tf(v.x));
        o.y = __uint_as_float(f2tf(v.y));
        o.z = __uint_as_float(f2tf(v.z));
        o.w = __uint_as_float(f2tf(v.w));
        dst[i] = o;
    }
}

// ---------------- fused dual GEMM (s1 = X@W1^T, s2 = X@W2^T) + act epilogue ------
// Block: 128(M) x 128(N) for BOTH outputs. 512 threads, 16 warps 4(M)x4(N),
// warp tile 32x32 per output. 3-stage cp.async, single sync per ktile.
// Epilogue: h = silu(acc1+b1)*(acc2+b2) -> g_s1 (tf32 bits). No s1/s2 round-trip.
__global__ __launch_bounds__(512, 1) void gemm01_kernel(const float* __restrict__ W1,
                                                        const float* __restrict__ W2,
                                                        const float* __restrict__ bias1,
                                                        const float* __restrict__ bias2) {
    constexpr int K = EMB;
    constexpr int NKT = K / 32;
    constexpr int NSTG = 3;
    constexpr int STAGEF = (128 + 256) * LDSR;   // A(128) + B1(128) + B2(128) rows

    int e = blockIdx.z;
    int cnt = g_cnt[e];
    int mt = blockIdx.y;
    if (mt * 128 >= cnt) return;

    const float* Ae  = g_xa + ((size_t)e * CAP + (size_t)mt * 128) * K;
    const float* B1e = W1 + ((size_t)e * HID + (size_t)blockIdx.x * 128) * K;
    const float* B2e = W2 + ((size_t)e * HID + (size_t)blockIdx.x * 128) * K;
    int n0 = blockIdx.x * 128;

    extern __shared__ float smem[];

    int tid = threadIdx.x, lane = tid & 31, wid = tid >> 5;
    int wm = wid & 3, wn = wid >> 2;   // 4(M) x 4(N) warps -> 32x32 warp tile

    float acc1[2][4][4], acc2[2][4][4];
#pragma unroll
    for (int m = 0; m < 2; m++)
#pragma unroll
        for (int n = 0; n < 4; n++)
#pragma unroll
            for (int i = 0; i < 4; i++) { acc1[m][n][i] = 0.f; acc2[m][n][i] = 0.f; }

    auto load_stage = [&](int s, int kt) {
        float* st = smem + s * STAGEF;
        const float* Ag  = Ae  + kt * 32;
        const float* B1g = B1e + kt * 32;
        const float* B2g = B2e + kt * 32;
#pragma unroll
        for (int i = 0; i < 2; i++) {            // A: 128 rows x 8 chunks
            int idx = tid + i * 512;
            int r = idx >> 3, c4 = (idx & 7) * 4;
            cpa16(&st[r * LDSR + c4], Ag + (size_t)r * K + c4);
        }
#pragma unroll
        for (int i = 0; i < 2; i++) {            // B1: 128 rows
            int idx = tid + i * 512;
            int r = idx >> 3, c4 = (idx & 7) * 4;
            cpa16(&st[(128 + r) * LDSR + c4], B1g + (size_t)r * K + c4);
        }
#pragma unroll
        for (int i = 0; i < 2; i++) {            // B2: 128 rows
            int idx = tid + i * 512;
            int r = idx >> 3, c4 = (idx & 7) * 4;
            cpa16(&st[(256 + r) * LDSR + c4], B2g + (size_t)r * K + c4);
        }
        asm volatile("cp.async.commit_group;\n");
    };

    load_stage(0, 0);
    load_stage(1, 1);

    int buf = 0;
    for (int kt = 0; kt < NKT; kt++) {
        asm volatile("cp.async.wait_group 1;\n" ::: "memory");
        __syncthreads();
        // refill the stage consumed two iterations ago
        if (kt + NSTG - 1 < NKT) load_stage((kt + NSTG - 1) % NSTG, kt + NSTG - 1);
        else asm volatile("cp.async.commit_group;\n");

        const float* st = smem + buf * STAGEF;
#pragma unroll
        for (int ks = 0; ks < 4; ks++) {
            int kc = ks * 8 + (lane & 3);
            uint32_t af[2][4];
#pragma unroll
            for (int m = 0; m < 2; m++) {
                int r = wm * 32 + m * 16 + (lane >> 2);
                af[m][0] = __float_as_uint(st[r * LDSR + kc]);          // pre-converted tf32
                af[m][1] = __float_as_uint(st[(r + 8) * LDSR + kc]);
                af[m][2] = __float_as_uint(st[r * LDSR + kc + 4]);
                af[m][3] = __float_as_uint(st[(r + 8) * LDSR + kc + 4]);
            }
            {
                uint32_t bf[4][2];
#pragma unroll
                for (int n = 0; n < 4; n++) {
                    int cn = 128 + wn * 32 + n * 8 + (lane >> 2);
                    bf[n][0] = f2tf(st[cn * LDSR + kc]);
                    bf[n][1] = f2tf(st[cn * LDSR + kc + 4]);
                }
#pragma unroll
                for (int m = 0; m < 2; m++)
#pragma unroll
                    for (int n = 0; n < 4; n++) mma_tf32(acc1[m][n], af[m], bf[n]);
            }
            {
                uint32_t bf[4][2];
#pragma unroll
                for (int n = 0; n < 4; n++) {
                    int cn = 256 + wn * 32 + n * 8 + (lane >> 2);
                    bf[n][0] = f2tf(st[cn * LDSR + kc]);
                    bf[n][1] = f2tf(st[cn * LDSR + kc + 4]);
                }
#pragma unroll
                for (int m = 0; m < 2; m++)
#pragma unroll
                    for (int n = 0; n < 4; n++) mma_tf32(acc2[m][n], af[m], bf[n]);
            }
        }
        buf = (buf == NSTG - 1) ? 0 : buf + 1;
    }

    // ---- fused activation epilogue: h = silu(s1+b1)*(s2+b2) -> g_s1 (tf32 bits) ----
    const float* b1p = bias1 + (size_t)e * HID;
    const float* b2p = bias2 + (size_t)e * HID;
#pragma unroll
    for (int m = 0; m < 2; m++) {
#pragma unroll
        for (int half = 0; half < 2; half++) {
            int r = wm * 32 + m * 16 + (lane >> 2) + half * 8;
            float* s1row = g_s1 + ((size_t)e * CAP + (size_t)mt * 128 + r) * (size_t)HID;
#pragma unroll
            for (int n = 0; n < 4; n++) {
                int col = n0 + wn * 32 + n * 8 + (lane & 3) * 2;
                float2 b1v = *(const float2*)(b1p + col);
                float2 b2v = *(const float2*)(b2p + col);
                float h0 = silu_mul(acc1[m][n][2 * half + 0] + b1v.x,
                                    acc2[m][n][2 * half + 0] + b2v.x);
                float h1 = silu_mul(acc1[m][n][2 * half + 1] + b1v.y,
                                    acc2[m][n][2 * half + 1] + b2v.y);
                float2 o;
                o.x = __uint_as_float(f2tf(h0));
                o.y = __uint_as_float(f2tf(h1));
                *(float2*)(s1row + col) = o;
            }
        }
    }
}

// ---------------- GEMM-2 (Y = H@W3^T) with fused gate-scatter epilogue ----------
// 128x128 tile, 256 threads, 8 warps 2(M)x4(N), warp tile 64x32, 3-stage,
// single sync per ktile, 2 CTAs/SM. Epilogue: atomicAdd(out[t], gate*(acc+b3)).
// Determinism: each out element gets exactly 2 adds onto an exact 0 -> order-invariant.
__global__ __launch_bounds__(256, 2) void gemm2_kernel(const float* __restrict__ W3,
                                                       const float* __restrict__ b3,
                                                       float* __restrict__ out) {
    constexpr int K = HID;
    constexpr int N = EMB;
    constexpr int NKT = K / 32;
    constexpr int NSTG = 3;
    constexpr int STAGEF = (128 + 128) * LDSR;

    int e = blockIdx.z;
    int cnt = g_cnt[e];
    int mt = blockIdx.y;
    if (mt * 128 >= cnt) return;

    const float* Ae = g_s1 + ((size_t)e * CAP + (size_t)mt * 128) * K;
    const float* Be = W3 + ((size_t)e * N + (size_t)blockIdx.x * 128) * K;
    int n0 = blockIdx.x * 128;

    extern __shared__ float smem[];

    int tid = threadIdx.x, lane = tid & 31, wid = tid >> 5;
    int wm = wid & 1, wn = wid >> 1;   // 2(M) x 4(N) warps -> 64x32 warp tile

    float acc[4][4][4];
#pragma unroll
    for (int m = 0; m < 4; m++)
#pragma unroll
        for (int n = 0; n < 4; n++)
#pragma unroll
            for (int i = 0; i < 4; i++) acc[m][n][i] = 0.f;

    auto load_stage = [&](int s, int kt) {
        float* Ab = smem + s * STAGEF;
        float* Bb = Ab + 128 * LDSR;
        const float* Ag = Ae + kt * 32;
        const float* Bg = Be + kt * 32;
#pragma unroll
        for (int i = 0; i < 4; i++) {
            int idx = tid + i * 256;
            int r = idx >> 3, c4 = (idx & 7) * 4;
            cpa16(&Ab[r * LDSR + c4], Ag + (size_t)r * K + c4);
            cpa16(&Bb[r * LDSR + c4], Bg + (size_t)r * K + c4);
        }
        asm volatile("cp.async.commit_group;\n");
    };

    load_stage(0, 0);
    load_stage(1, 1);

    int buf = 0;
    for (int kt = 0; kt < NKT; kt++) {
        asm volatile("cp.async.wait_group 1;\n" ::: "memory");
        __syncthreads();
        if (kt + NSTG - 1 < NKT) load_stage((kt + NSTG - 1) % NSTG, kt + NSTG - 1);
        else asm volatile("cp.async.commit_group;\n");

        const float* Asb = smem + buf * STAGEF;
        const float* Bsb = Asb + 128 * LDSR;
#pragma unroll
        for (int ks = 0; ks < 4; ks++) {
            uint32_t af[4][4], bf[4][2];
            int kc = ks * 8 + (lane & 3);
#pragma unroll
            for (int m = 0; m < 4; m++) {
                int r = wm * 64 + m * 16 + (lane >> 2);
                af[m][0] = __float_as_uint(Asb[r * LDSR + kc]);         // h is tf32 bits
                af[m][1] = __float_as_uint(Asb[(r + 8) * LDSR + kc]);
                af[m][2] = __float_as_uint(Asb[r * LDSR + kc + 4]);
                af[m][3] = __float_as_uint(Asb[(r + 8) * LDSR + kc + 4]);
            }
#pragma unroll
            for (int n = 0; n < 4; n++) {
                int cn = wn * 32 + n * 8 + (lane >> 2);
                bf[n][0] = f2tf(Bsb[cn * LDSR + kc]);
                bf[n][1] = f2tf(Bsb[cn * LDSR + kc + 4]);
            }
#pragma unroll
            for (int m = 0; m < 4; m++)
#pragma unroll
                for (int n = 0; n < 4; n++) mma_tf32(acc[m][n], af[m], bf[n]);
        }
        buf = (buf == NSTG - 1) ? 0 : buf + 1;
    }

    // ---- scatter epilogue: out[tok] += gate * (acc + b3) (RED.ADD, 2 adds/elem) ----
    const float* b3p = b3 + (size_t)e * EMB;
#pragma unroll
    for (int m = 0; m < 4; m++) {
#pragma unroll
        for (int half = 0; half < 2; half++) {
            int r = wm * 64 + m * 16 + (lane >> 2) + half * 8;
            int slot = mt * 128 + r;
            if (slot < cnt) {
                int t = g_tok[e * CAP + slot];
                float gate = g_slotgate[e * CAP + slot];
                float* orow = out + (size_t)t * EMB;
#pragma unroll
                for (int n = 0; n < 4; n++) {
                    int col = n0 + wn * 32 + n * 8 + (lane & 3) * 2;
                    atomicAdd(orow + col,     gate * (acc[m][n][2 * half + 0] + b3p[col]));
                    atomicAdd(orow + col + 1, gate * (acc[m][n][2 * half + 1] + b3p[col + 1]));
                }
            }
        }
    }
}

__global__ void aux_kernel(float* __restrict__ out, int out_size) {
    if (threadIdx.x == 0 && blockIdx.x == 0 && out_size > TOKS * EMB) {
        float a = 0.f;
        for (int e = 0; e < NE; e++)
            a += ((float)g_cnt[e] / (float)TOKS) * (g_sumprob[e] / (float)TOKS);
        out[TOKS * EMB] = (float)NE * a;
    }
}

// ---------------- launcher ----------------
extern "C" void kernel_launch(void* const* d_in, const int* in_sizes, int n_in,
                              void* d_out, int out_size) {
    const float* x  = (const float*)d_in[0];
    const float* gw = (const float*)d_in[1];
    const float* w1 = (const float*)d_in[2];
    const float* b1 = (const float*)d_in[3];
    const float* w2 = (const float*)d_in[4];
    const float* b2 = (const float*)d_in[5];
    const float* w3 = (const float*)d_in[6];
    const float* b3 = (const float*)d_in[7];
    float* out = (float*)d_out;

    const int SMEM01 = 3 * (128 + 256) * LDSR * 4;   // 165888
    const int SMEM2  = 3 * (128 + 128) * LDSR * 4;   // 110592

    cudaFuncSetAttribute(gemm01_kernel, cudaFuncAttributeMaxDynamicSharedMemorySize, SMEM01);
    cudaFuncSetAttribute(gemm2_kernel,  cudaFuncAttributeMaxDynamicSharedMemorySize, SMEM2);

    init_kernel<<<1, 32>>>();
    router_kernel<<<TOKS / 8, 256>>>(x, gw);
    gather_kernel<<<NE * CAP / 8, 256>>>(x);
    gemm01_kernel<<<dim3(HID / 128, CAP / 128, NE), 512, SMEM01>>>(w1, w2, b1, b2);
    zero_out_kernel<<<1024, 256>>>((float4*)out);
    gemm2_kernel<<<dim3(EMB / 128, CAP / 128, NE), 256, SMEM2>>>(w3, b3, out);
    aux_kernel<<<1, 32>>>(out, out_size);
}

// round 16
// speedup vs baseline: 1.3854x; 1.0239x over previous
#include <cuda_runtime.h>
#include <cstdint>
#include <cstddef>

#define TOKS 4096
#define EMB  1024
#define HID  4096
#define NE   8
#define CAP  4096
#define LDSR 36          // padded smem row stride (floats)
#define NSTG 3

// ---------------- scratch (device globals; no allocations allowed) ----------------
__device__ int   g_cnt[NE];
__device__ float g_sumprob[NE];
__device__ int   g_tok[NE * CAP];
__device__ float g_slotgate[NE * CAP];           // per-slot gate weight
__device__ float g_xa[(size_t)NE * CAP * EMB];   // gathered activations, tf32 bits
__device__ float g_s1[(size_t)NE * CAP * HID];   // X@W1^T fp32, then h (tf32 bits, in-place)

// ---------------- helpers ----------------
__device__ __forceinline__ uint32_t f2tf(float f) {
    uint32_t u;
    asm("cvt.rna.tf32.f32 %0, %1;" : "=r"(u) : "f"(f));
    return u;
}
__device__ __forceinline__ void cpa16(void* s, const void* g) {
    uint32_t sa = (uint32_t)__cvta_generic_to_shared(s);
    asm volatile("cp.async.cg.shared.global [%0], [%1], 16;\n" :: "r"(sa), "l"(g));
}
__device__ __forceinline__ void mma_tf32(float* c, const uint32_t* a, const uint32_t* b) {
    asm volatile(
        "mma.sync.aligned.m16n8k8.row.col.f32.tf32.tf32.f32 "
        "{%0,%1,%2,%3}, {%4,%5,%6,%7}, {%8,%9}, {%0,%1,%2,%3};\n"
        : "+f"(c[0]), "+f"(c[1]), "+f"(c[2]), "+f"(c[3])
        : "r"(a[0]), "r"(a[1]), "r"(a[2]), "r"(a[3]), "r"(b[0]), "r"(b[1]));
}
__device__ __forceinline__ float silu_mul(float a, float b) {
    return (a / (1.f + expf(-a))) * b;
}

// ---------------- small kernels ----------------
__global__ void init_kernel() {
    int i = threadIdx.x;
    if (i < NE) { g_cnt[i] = 0; g_sumprob[i] = 0.f; }
}

__global__ void zero_out_kernel(float4* __restrict__ out) {
    int i = blockIdx.x * blockDim.x + threadIdx.x;
    int stride = gridDim.x * blockDim.x;
    const int n4 = TOKS * EMB / 4;
    for (; i < n4; i += stride) out[i] = make_float4(0.f, 0.f, 0.f, 0.f);
}

// one warp per token: scores, top-2, softmax gates, slot assignment, aux accumulation
__global__ void router_kernel(const float* __restrict__ x, const float* __restrict__ gw) {
    __shared__ float s_ps[NE];
    int tid = threadIdx.x, lane = tid & 31, wid = tid >> 5;
    if (tid < NE) s_ps[tid] = 0.f;
    __syncthreads();

    int t = blockIdx.x * 8 + wid;
    float acc[NE];
#pragma unroll
    for (int e = 0; e < NE; e++) acc[e] = 0.f;
    const float* xr = x + (size_t)t * EMB;
    for (int i = lane; i < EMB; i += 32) {
        float xi = xr[i];
#pragma unroll
        for (int e = 0; e < NE; e++) acc[e] += xi * gw[e * EMB + i];
    }
#pragma unroll
    for (int e = 0; e < NE; e++) {
#pragma unroll
        for (int o = 16; o > 0; o >>= 1) acc[e] += __shfl_xor_sync(0xffffffffu, acc[e], o);
    }
    if (lane == 0) {
        float m = acc[0];
#pragma unroll
        for (int e = 1; e < NE; e++) m = fmaxf(m, acc[e]);
        float pe[NE], se = 0.f;
#pragma unroll
        for (int e = 0; e < NE; e++) { pe[e] = expf(acc[e] - m); se += pe[e]; }
        float inv = 1.f / se;
#pragma unroll
        for (int e = 0; e < NE; e++) atomicAdd(&s_ps[e], pe[e] * inv);

        // top-2 (ties: lowest index first, matching jax top_k)
        int i1 = 0;
#pragma unroll
        for (int e = 1; e < NE; e++) if (acc[e] > acc[i1]) i1 = e;
        int i2 = (i1 == 0) ? 1 : 0;
#pragma unroll
        for (int e = 0; e < NE; e++) if (e != i1 && acc[e] > acc[i2]) i2 = e;

        float p1 = 1.f / (1.f + expf(acc[i2] - acc[i1]));
        float p2 = 1.f - p1;
        int s1 = atomicAdd(&g_cnt[i1], 1);
        int s2 = atomicAdd(&g_cnt[i2], 1);
        g_tok[i1 * CAP + s1] = t;
        g_tok[i2 * CAP + s2] = t;
        g_slotgate[i1 * CAP + s1] = p1;
        g_slotgate[i2 * CAP + s2] = p2;
    }
    __syncthreads();
    if (tid < NE) atomicAdd(&g_sumprob[tid], s_ps[tid]);
}

// one warp per (expert, slot): copy token row into expert-contiguous scratch (tf32 bits)
__global__ void gather_kernel(const float* __restrict__ x) {
    int w = (blockIdx.x * blockDim.x + threadIdx.x) >> 5;
    int lane = threadIdx.x & 31;
    int e = w >> 12, s = w & (CAP - 1);
    if (s >= g_cnt[e]) return;
    int t = g_tok[w];
    const float4* src = (const float4*)(x + (size_t)t * EMB);
    float4* dst = (float4*)(g_xa + (size_t)w * EMB);
#pragma unroll 4
    for (int i = lane; i < EMB / 4; i += 32) {
        float4 v = src[i];
        float4 o;
        o.x = __uint_as_float(f2tf(v.x));
        o.y = __uint_as_float(f2tf(v.y));
        o.z = __uint_as_float(f2tf(v.z));
        o.w = __uint_as_float(f2tf(v.w));
        dst[i] = o;
    }
}

// ---------------- grouped GEMM: 128x128x32 tiles, 8 warps 2(M)x4(N), 64x32 warp tile
// 3-stage cp.async, SINGLE sync per ktile, 2 CTAs/SM.
// MODE 0: A=g_xa (K=EMB), W=w1, epilogue: raw fp32 -> g_s1
// MODE 1: A=g_xa (K=EMB), W=w2, epilogue: h=silu(s1+b1)*(acc+b2) -> g_s1 (tf32 bits)
// MODE 2: A=g_s1 (K=HID), W=w3, epilogue: atomicAdd(out[tok], gate*(acc+b3))
template <int MODE>
__global__ __launch_bounds__(256, 2) void gemm_kernel(const float* __restrict__ W,
                                                      const float* __restrict__ bias1,
                                                      const float* __restrict__ bias2,
                                                      float* __restrict__ out) {
    constexpr int K = (MODE == 2) ? HID : EMB;
    constexpr int N = (MODE == 2) ? EMB : HID;
    constexpr int NKT = K / 32;
    constexpr int STAGEF = (128 + 128) * LDSR;

    int e = blockIdx.z;
    int cnt = g_cnt[e];
    int mt = blockIdx.y;
    if (mt * 128 >= cnt) return;

    const float* A = (MODE == 2) ? g_s1 : g_xa;
    const float* Ae = A + ((size_t)e * CAP + (size_t)mt * 128) * K;
    const float* Be = W + ((size_t)e * N + (size_t)blockIdx.x * 128) * K;
    int n0 = blockIdx.x * 128;

    extern __shared__ float smem[];

    int tid = threadIdx.x, lane = tid & 31, wid = tid >> 5;
    int wm = wid & 1, wn = wid >> 1;   // 2(M) x 4(N) warps -> 64x32 warp tile

    float acc[4][4][4];
#pragma unroll
    for (int m = 0; m < 4; m++)
#pragma unroll
        for (int n = 0; n < 4; n++)
#pragma unroll
            for (int i = 0; i < 4; i++) acc[m][n][i] = 0.f;

    auto load_stage = [&](int s, int kt) {
        float* Ab = smem + s * STAGEF;
        float* Bb = Ab + 128 * LDSR;
        const float* Ag = Ae + kt * 32;
        const float* Bg = Be + kt * 32;
#pragma unroll
        for (int i = 0; i < 4; i++) {
            int idx = tid + i * 256;
            int r = idx >> 3, c4 = (idx & 7) * 4;
            cpa16(&Ab[r * LDSR + c4], Ag + (size_t)r * K + c4);
            cpa16(&Bb[r * LDSR + c4], Bg + (size_t)r * K + c4);
        }
        asm volatile("cp.async.commit_group;\n");
    };

    load_stage(0, 0);
    load_stage(1, 1);

    int buf = 0;
    for (int kt = 0; kt < NKT; kt++) {
        // newest outstanding group = load of stage kt+1; stage kt is complete
        asm volatile("cp.async.wait_group 1;\n" ::: "memory");
        __syncthreads();
        // stage (kt+2)%3 == stage (kt-1)%3: all warps finished reading it before
        // this barrier, so refill is safe without a second barrier.
        if (kt + 2 < NKT) load_stage((kt + 2) % NSTG, kt + 2);
        else asm volatile("cp.async.commit_group;\n");   // keep group count aligned

        const float* Asb = smem + buf * STAGEF;
        const float* Bsb = Asb + 128 * LDSR;
#pragma unroll
        for (int ks = 0; ks < 4; ks++) {
            uint32_t af[4][4], bf[4][2];
            int kc = ks * 8 + (lane & 3);
#pragma unroll
            for (int m = 0; m < 4; m++) {
                int r = wm * 64 + m * 16 + (lane >> 2);
                af[m][0] = __float_as_uint(Asb[r * LDSR + kc]);         // pre-converted tf32
                af[m][1] = __float_as_uint(Asb[(r + 8) * LDSR + kc]);
                af[m][2] = __float_as_uint(Asb[r * LDSR + kc + 4]);
                af[m][3] = __float_as_uint(Asb[(r + 8) * LDSR + kc + 4]);
            }
#pragma unroll
            for (int n = 0; n < 4; n++) {
                int cn = wn * 32 + n * 8 + (lane >> 2);
                bf[n][0] = f2tf(Bsb[cn * LDSR + kc]);
                bf[n][1] = f2tf(Bsb[cn * LDSR + kc + 4]);
            }
#pragma unroll
            for (int m = 0; m < 4; m++)
#pragma unroll
                for (int n = 0; n < 4; n++) mma_tf32(acc[m][n], af[m], bf[n]);
        }
        buf = (buf == NSTG - 1) ? 0 : buf + 1;
    }

    // ---- epilogues ----
    if (MODE == 1) {
        // h = silu(s1+b1)*(acc+b2) stored as tf32 bits in-place into g_s1
        const float* b1p = bias1 + (size_t)e * HID;
        const float* b2p = bias2 + (size_t)e * HID;
#pragma unroll
        for (int m = 0; m < 4; m++) {
#pragma unroll
            for (int half = 0; half < 2; half++) {
                int r = wm * 64 + m * 16 + (lane >> 2) + half * 8;
                float* s1row = g_s1 + ((size_t)e * CAP + (size_t)mt * 128 + r) * (size_t)HID;
#pragma unroll
                for (int n = 0; n < 4; n++) {
                    int col = n0 + wn * 32 + n * 8 + (lane & 3) * 2;
                    float2 s1v = *(const float2*)(s1row + col);
                    float2 b1v = *(const float2*)(b1p + col);
                    float2 b2v = *(const float2*)(b2p + col);
                    float h0 = silu_mul(s1v.x + b1v.x, acc[m][n][2 * half + 0] + b2v.x);
                    float h1 = silu_mul(s1v.y + b1v.y, acc[m][n][2 * half + 1] + b2v.y);
                    float2 o;
                    o.x = __uint_as_float(f2tf(h0));
                    o.y = __uint_as_float(f2tf(h1));
                    *(float2*)(s1row + col) = o;
                }
            }
        }
    } else if (MODE == 2) {
        // scatter: out[tok] += gate * (acc + b3); exactly 2 adds per element onto
        // exact 0 -> order-invariant, deterministic.
        const float* b3p = bias1 + (size_t)e * EMB;   // bias1 carries b3 for MODE 2
#pragma unroll
        for (int m = 0; m < 4; m++) {
#pragma unroll
            for (int half = 0; half < 2; half++) {
                int r = wm * 64 + m * 16 + (lane >> 2) + half * 8;
                int slot = mt * 128 + r;
                if (slot < cnt) {
                    int t = g_tok[e * CAP + slot];
                    float gate = g_slotgate[e * CAP + slot];
                    float* orow = out + (size_t)t * EMB;
#pragma unroll
                    for (int n = 0; n < 4; n++) {
                        int col = n0 + wn * 32 + n * 8 + (lane & 3) * 2;
                        atomicAdd(orow + col,     gate * (acc[m][n][2 * half + 0] + b3p[col]));
                        atomicAdd(orow + col + 1, gate * (acc[m][n][2 * half + 1] + b3p[col + 1]));
                    }
                }
            }
        }
    } else {
        // raw fp32 -> g_s1
#pragma unroll
        for (int m = 0; m < 4; m++) {
#pragma unroll
            for (int half = 0; half < 2; half++) {
                int r = wm * 64 + m * 16 + (lane >> 2) + half * 8;
                float* Crow = g_s1 + ((size_t)e * CAP + (size_t)mt * 128 + r) * (size_t)HID;
#pragma unroll
                for (int n = 0; n < 4; n++) {
                    int col = n0 + wn * 32 + n * 8 + (lane & 3) * 2;
                    float2 o = make_float2(acc[m][n][2 * half + 0], acc[m][n][2 * half + 1]);
                    *(float2*)(Crow + col) = o;
                }
            }
        }
    }
}

__global__ void aux_kernel(float* __restrict__ out, int out_size) {
    if (threadIdx.x == 0 && blockIdx.x == 0 && out_size > TOKS * EMB) {
        float a = 0.f;
        for (int e = 0; e < NE; e++)
            a += ((float)g_cnt[e] / (float)TOKS) * (g_sumprob[e] / (float)TOKS);
        out[TOKS * EMB] = (float)NE * a;
    }
}

// ---------------- launcher ----------------
extern "C" void kernel_launch(void* const* d_in, const int* in_sizes, int n_in,
                              void* d_out, int out_size) {
    const float* x  = (const float*)d_in[0];
    const float* gw = (const float*)d_in[1];
    const float* w1 = (const float*)d_in[2];
    const float* b1 = (const float*)d_in[3];
    const float* w2 = (const float*)d_in[4];
    const float* b2 = (const float*)d_in[5];
    const float* w3 = (const float*)d_in[6];
    const float* b3 = (const float*)d_in[7];
    float* out = (float*)d_out;

    const int SMEM_BYTES = NSTG * (128 + 128) * LDSR * 4;   // 110592

    cudaFuncSetAttribute(gemm_kernel<0>, cudaFuncAttributeMaxDynamicSharedMemorySize, SMEM_BYTES);
    cudaFuncSetAttribute(gemm_kernel<1>, cudaFuncAttributeMaxDynamicSharedMemorySize, SMEM_BYTES);
    cudaFuncSetAttribute(gemm_kernel<2>, cudaFuncAttributeMaxDynamicSharedMemorySize, SMEM_BYTES);

    init_kernel<<<1, 32>>>();
    router_kernel<<<TOKS / 8, 256>>>(x, gw);
    gather_kernel<<<NE * CAP / 8, 256>>>(x);
    gemm_kernel<0><<<dim3(HID / 128, CAP / 128, NE), 256, SMEM_BYTES>>>(w1, nullptr, nullptr, nullptr);
    gemm_kernel<1><<<dim3(HID / 128, CAP / 128, NE), 256, SMEM_BYTES>>>(w2, b1, b2, nullptr);
    zero_out_kernel<<<1024, 256>>>((float4*)out);
    gemm_kernel<2><<<dim3(EMB / 128, CAP / 128, NE), 256, SMEM_BYTES>>>(w3, b3, nullptr, out);
    aux_kernel<<<1, 32>>>(out, out_size);
}

// round 17
// speedup vs baseline: 1.8138x; 1.3092x over previous
#include <cuda_runtime.h>
#include <cuda_fp16.h>
#include <cstdint>
#include <cstddef>

#define TOKS 4096
#define EMB  1024
#define HID  4096
#define NE   8
#define CAP  4096
#define LDSR 36              // B smem row stride (floats)
#define LDSA_B 80            // A smem row stride (bytes) = 40 halves; 16B-aligned, conflict-free
#define A_STAGE_B (128 * LDSA_B)            // 10240
#define B_STAGE_B (128 * LDSR * 4)          // 18432
#define STAGE_B   (A_STAGE_B + B_STAGE_B)   // 28672

// ---------------- scratch (device globals; no allocations allowed) ----------------
__device__ int    g_cnt[NE];
__device__ float  g_sumprob[NE];
__device__ int    g_tok[NE * CAP];
__device__ int    g_map[TOKS * 2];
__device__ float  g_gatew[TOKS * 2];
__device__ __half g_xa[(size_t)NE * CAP * EMB];   // gathered activations (fp16)
__device__ float  g_s1[(size_t)NE * CAP * HID];   // X@W1^T fp32
__device__ __half g_h [(size_t)NE * CAP * HID];   // h = silu(s1+b1)*(s2+b2) (fp16)
__device__ float  g_y [(size_t)NE * CAP * EMB];   // H@W3^T fp32

// ---------------- helpers ----------------
__device__ __forceinline__ void cpa16(void* s, const void* g) {
    uint32_t sa = (uint32_t)__cvta_generic_to_shared(s);
    asm volatile("cp.async.cg.shared.global [%0], [%1], 16;\n" :: "r"(sa), "l"(g));
}
__device__ __forceinline__ uint32_t packh2(float lo, float hi) {
    uint32_t u;
    asm("cvt.rn.f16x2.f32 %0, %1, %2;" : "=r"(u) : "f"(hi), "f"(lo));
    return u;
}
__device__ __forceinline__ void mma_f16(float* c, const uint32_t* a, const uint32_t* b) {
    asm volatile(
        "mma.sync.aligned.m16n8k16.row.col.f32.f16.f16.f32 "
        "{%0,%1,%2,%3}, {%4,%5,%6,%7}, {%8,%9}, {%0,%1,%2,%3};\n"
        : "+f"(c[0]), "+f"(c[1]), "+f"(c[2]), "+f"(c[3])
        : "r"(a[0]), "r"(a[1]), "r"(a[2]), "r"(a[3]), "r"(b[0]), "r"(b[1]));
}
__device__ __forceinline__ float silu_mul(float a, float b) {
    return (a / (1.f + expf(-a))) * b;
}

// ---------------- small kernels ----------------
__global__ void init_kernel() {
    int i = threadIdx.x;
    if (i < NE) { g_cnt[i] = 0; g_sumprob[i] = 0.f; }
}

// one warp per token: scores, top-2, softmax gates, slot assignment, aux accumulation
__global__ void router_kernel(const float* __restrict__ x, const float* __restrict__ gw) {
    __shared__ float s_ps[NE];
    int tid = threadIdx.x, lane = tid & 31, wid = tid >> 5;
    if (tid < NE) s_ps[tid] = 0.f;
    __syncthreads();

    int t = blockIdx.x * 8 + wid;
    float acc[NE];
#pragma unroll
    for (int e = 0; e < NE; e++) acc[e] = 0.f;
    const float* xr = x + (size_t)t * EMB;
    for (int i = lane; i < EMB; i += 32) {
        float xi = xr[i];
#pragma unroll
        for (int e = 0; e < NE; e++) acc[e] += xi * gw[e * EMB + i];
    }
#pragma unroll
    for (int e = 0; e < NE; e++) {
#pragma unroll
        for (int o = 16; o > 0; o >>= 1) acc[e] += __shfl_xor_sync(0xffffffffu, acc[e], o);
    }
    if (lane == 0) {
        float m = acc[0];
#pragma unroll
        for (int e = 1; e < NE; e++) m = fmaxf(m, acc[e]);
        float pe[NE], se = 0.f;
#pragma unroll
        for (int e = 0; e < NE; e++) { pe[e] = expf(acc[e] - m); se += pe[e]; }
        float inv = 1.f / se;
#pragma unroll
        for (int e = 0; e < NE; e++) atomicAdd(&s_ps[e], pe[e] * inv);

        // top-2 (ties: lowest index first, matching jax top_k)
        int i1 = 0;
#pragma unroll
        for (int e = 1; e < NE; e++) if (acc[e] > acc[i1]) i1 = e;
        int i2 = (i1 == 0) ? 1 : 0;
#pragma unroll
        for (int e = 0; e < NE; e++) if (e != i1 && acc[e] > acc[i2]) i2 = e;

        float p1 = 1.f / (1.f + expf(acc[i2] - acc[i1]));
        float p2 = 1.f - p1;
        int s1 = atomicAdd(&g_cnt[i1], 1);
        int s2 = atomicAdd(&g_cnt[i2], 1);
        g_tok[i1 * CAP + s1] = t;
        g_tok[i2 * CAP + s2] = t;
        g_map[t * 2 + 0] = i1 * CAP + s1;
        g_map[t * 2 + 1] = i2 * CAP + s2;
        g_gatew[t * 2 + 0] = p1;
        g_gatew[t * 2 + 1] = p2;
    }
    __syncthreads();
    if (tid < NE) atomicAdd(&g_sumprob[tid], s_ps[tid]);
}

// one warp per (expert, slot): copy token row into expert-contiguous scratch as fp16
__global__ void gather_kernel(const float* __restrict__ x) {
    int w = (blockIdx.x * blockDim.x + threadIdx.x) >> 5;
    int lane = threadIdx.x & 31;
    int e = w >> 12, s = w & (CAP - 1);
    if (s >= g_cnt[e]) return;
    int t = g_tok[w];
    const float4* src = (const float4*)(x + (size_t)t * EMB);
    uint2* dst = (uint2*)(g_xa + (size_t)w * EMB);
#pragma unroll 4
    for (int i = lane; i < EMB / 4; i += 32) {
        float4 v = src[i];
        uint2 o;
        o.x = packh2(v.x, v.y);
        o.y = packh2(v.z, v.w);
        dst[i] = o;
    }
}

// ---------------- grouped GEMM: 128x128x32 tiles, fp16 MMA (m16n8k16), fp32 accum --
// 8 warps 2(M)x4(N), 64x32 warp tile, 2-stage cp.async, 2 CTAs/SM.
// A operand fp16 (g_xa / g_h); B (weights) fp32 in smem, packed to f16x2 at frag load.
// MODE 0: A=g_xa (K=EMB), W=w1, epilogue: raw fp32 -> g_s1
// MODE 1: A=g_xa (K=EMB), W=w2, epilogue: h=silu(s1+b1)*(acc+b2) -> g_h (fp16)
// MODE 2: A=g_h  (K=HID), W=w3, epilogue: raw fp32 -> g_y
template <int MODE>
__global__ __launch_bounds__(256, 2) void gemm_kernel(const float* __restrict__ W,
                                                      const float* __restrict__ bias1,
                                                      const float* __restrict__ bias2) {
    constexpr int K = (MODE == 2) ? HID : EMB;
    constexpr int N = (MODE == 2) ? EMB : HID;
    constexpr int NKT = K / 32;

    int e = blockIdx.z;
    int cnt = g_cnt[e];
    int mt = blockIdx.y;
    if (mt * 128 >= cnt) return;

    const __half* A = (MODE == 2) ? g_h : g_xa;
    const __half* Ae = A + ((size_t)e * CAP + (size_t)mt * 128) * K;
    const float* Be = W + ((size_t)e * N + (size_t)blockIdx.x * 128) * K;
    int n0 = blockIdx.x * 128;

    extern __shared__ char dsm[];

    int tid = threadIdx.x, lane = tid & 31, wid = tid >> 5;
    int wm = wid & 1, wn = wid >> 1;   // 2(M) x 4(N) warps -> 64x32 warp tile
    int tg = lane & 3, gid = lane >> 2;

    float acc[4][4][4];
#pragma unroll
    for (int m = 0; m < 4; m++)
#pragma unroll
        for (int n = 0; n < 4; n++)
#pragma unroll
            for (int i = 0; i < 4; i++) acc[m][n][i] = 0.f;

    auto load_stage = [&](int s, int kt) {
        char* sb = dsm + s * STAGE_B;
        const __half* Ag = Ae + kt * 32;
        const float* Bg = Be + kt * 32;
        // A: 128 rows x 64B (32 halves) = 512 chunks of 16B
#pragma unroll
        for (int i = 0; i < 2; i++) {
            int idx = tid + i * 256;
            int r = idx >> 2, c = idx & 3;
            cpa16(sb + r * LDSA_B + c * 16, Ag + (size_t)r * K + c * 8);
        }
        // B: 128 rows x 128B (32 floats) = 1024 chunks of 16B
        float* Bb = (float*)(sb + A_STAGE_B);
#pragma unroll
        for (int i = 0; i < 4; i++) {
            int idx = tid + i * 256;
            int r = idx >> 3, c4 = (idx & 7) * 4;
            cpa16(&Bb[r * LDSR + c4], Bg + (size_t)r * K + c4);
        }
        asm volatile("cp.async.commit_group;\n");
    };

    load_stage(0, 0);

    for (int kt = 0; kt < NKT; kt++) {
        asm volatile("cp.async.wait_group 0;\n" ::: "memory");
        __syncthreads();
        if (kt + 1 < NKT) load_stage((kt + 1) & 1, kt + 1);

        const char* sb = dsm + (kt & 1) * STAGE_B;
        const uint32_t* Au = (const uint32_t*)sb;       // row stride 20 uints (40 halves)
        const float* Bs = (const float*)(sb + A_STAGE_B);
#pragma unroll
        for (int ks = 0; ks < 2; ks++) {                // K=16 per MMA step
            uint32_t af[4][4], bf[4][2];
            int ko = ks * 8 + tg;                        // uint offset within A row
#pragma unroll
            for (int m = 0; m < 4; m++) {
                int r = wm * 64 + m * 16 + gid;
                af[m][0] = Au[r * 20 + ko];
                af[m][1] = Au[(r + 8) * 20 + ko];
                af[m][2] = Au[r * 20 + ko + 4];
                af[m][3] = Au[(r + 8) * 20 + ko + 4];
            }
#pragma unroll
            for (int n = 0; n < 4; n++) {
                int cn = wn * 32 + n * 8 + gid;
                float2 v0 = *(const float2*)(Bs + cn * LDSR + ks * 16 + tg * 2);
                float2 v1 = *(const float2*)(Bs + cn * LDSR + ks * 16 + 8 + tg * 2);
                bf[n][0] = packh2(v0.x, v0.y);
                bf[n][1] = packh2(v1.x, v1.y);
            }
#pragma unroll
            for (int m = 0; m < 4; m++)
#pragma unroll
                for (int n = 0; n < 4; n++) mma_f16(acc[m][n], af[m], bf[n]);
        }
        __syncthreads();
    }

    // ---- epilogues (C fragment mapping: rows gid/gid+8, cols tg*2, tg*2+1) ----
    if (MODE == 1) {
        const float* b1p = bias1 + (size_t)e * HID;
        const float* b2p = bias2 + (size_t)e * HID;
#pragma unroll
        for (int m = 0; m < 4; m++) {
#pragma unroll
            for (int half = 0; half < 2; half++) {
                int r = wm * 64 + m * 16 + gid + half * 8;
                size_t grow = (size_t)e * CAP + (size_t)mt * 128 + r;
                const float* s1row = g_s1 + grow * (size_t)HID;
                __half* hrow = g_h + grow * (size_t)HID;
#pragma unroll
                for (int n = 0; n < 4; n++) {
                    int col = n0 + wn * 32 + n * 8 + tg * 2;
                    float2 s1v = *(const float2*)(s1row + col);
                    float2 b1v = *(const float2*)(b1p + col);
                    float2 b2v = *(const float2*)(b2p + col);
                    float h0 = silu_mul(s1v.x + b1v.x, acc[m][n][2 * half + 0] + b2v.x);
                    float h1 = silu_mul(s1v.y + b1v.y, acc[m][n][2 * half + 1] + b2v.y);
                    *(uint32_t*)(hrow + col) = packh2(h0, h1);
                }
            }
        }
    } else {
        float* C = (MODE == 0) ? g_s1 : g_y;
#pragma unroll
        for (int m = 0; m < 4; m++) {
#pragma unroll
            for (int half = 0; half < 2; half++) {
                int r = wm * 64 + m * 16 + gid + half * 8;
                float* Crow = C + ((size_t)e * CAP + (size_t)mt * 128 + r) * (size_t)N;
#pragma unroll
                for (int n = 0; n < 4; n++) {
                    int col = n0 + wn * 32 + n * 8 + tg * 2;
                    float2 o = make_float2(acc[m][n][2 * half + 0], acc[m][n][2 * half + 1]);
                    *(float2*)(Crow + col) = o;
                }
            }
        }
    }
}

// out[t] = sum_k gate_k * (Y[slot_k] + b3[e_k])   (one warp per token; fully writes d_out)
__global__ void combine_kernel(float* __restrict__ out, const float* __restrict__ b3) {
    int w = (blockIdx.x * blockDim.x + threadIdx.x) >> 5;
    int lane = threadIdx.x & 31;
    if (w >= TOKS) return;
    int m0 = g_map[2 * w], m1 = g_map[2 * w + 1];
    float p0 = g_gatew[2 * w], p1 = g_gatew[2 * w + 1];
    int e0 = m0 >> 12, e1 = m1 >> 12;
    const float4* y0 = (const float4*)(g_y + (size_t)m0 * EMB);
    const float4* y1 = (const float4*)(g_y + (size_t)m1 * EMB);
    const float4* bb0 = (const float4*)(b3 + (size_t)e0 * EMB);
    const float4* bb1 = (const float4*)(b3 + (size_t)e1 * EMB);
    float4* o = (float4*)(out + (size_t)w * EMB);
    for (int i = lane; i < EMB / 4; i += 32) {
        float4 a = y0[i], b = y1[i], c = bb0[i], d = bb1[i];
        float4 r;
        r.x = p0 * (a.x + c.x) + p1 * (b.x + d.x);
        r.y = p0 * (a.y + c.y) + p1 * (b.y + d.y);
        r.z = p0 * (a.z + c.z) + p1 * (b.z + d.z);
        r.w = p0 * (a.w + c.w) + p1 * (b.w + d.w);
        o[i] = r;
    }
}

__global__ void aux_kernel(float* __restrict__ out, int out_size) {
    if (threadIdx.x == 0 && blockIdx.x == 0 && out_size > TOKS * EMB) {
        float a = 0.f;
        for (int e = 0; e < NE; e++)
            a += ((float)g_cnt[e] / (float)TOKS) * (g_sumprob[e] / (float)TOKS);
        out[TOKS * EMB] = (float)NE * a;
    }
}

// ---------------- launcher ----------------
extern "C" void kernel_launch(void* const* d_in, const int* in_sizes, int n_in,
                              void* d_out, int out_size) {
    const float* x  = (const float*)d_in[0];
    const float* gw = (const float*)d_in[1];
    const float* w1 = (const float*)d_in[2];
    const float* b1 = (const float*)d_in[3];
    const float* w2 = (const float*)d_in[4];
    const float* b2 = (const float*)d_in[5];
    const float* w3 = (const float*)d_in[6];
    const float* b3 = (const float*)d_in[7];
    float* out = (float*)d_out;

    const int SMEM_BYTES = 2 * STAGE_B;   // 57344

    cudaFuncSetAttribute(gemm_kernel<0>, cudaFuncAttributeMaxDynamicSharedMemorySize, SMEM_BYTES);
    cudaFuncSetAttribute(gemm_kernel<1>, cudaFuncAttributeMaxDynamicSharedMemorySize, SMEM_BYTES);
    cudaFuncSetAttribute(gemm_kernel<2>, cudaFuncAttributeMaxDynamicSharedMemorySize, SMEM_BYTES);

    init_kernel<<<1, 32>>>();
    router_kernel<<<TOKS / 8, 256>>>(x, gw);
    gather_kernel<<<NE * CAP / 8, 256>>>(x);
    gemm_kernel<0><<<dim3(HID / 128, CAP / 128, NE), 256, SMEM_BYTES>>>(w1, nullptr, nullptr);
    gemm_kernel<1><<<dim3(HID / 128, CAP / 128, NE), 256, SMEM_BYTES>>>(w2, b1, b2);
    gemm_kernel<2><<<dim3(EMB / 128, CAP / 128, NE), 256, SMEM_BYTES>>>(w3, b3, nullptr);
    combine_kernel<<<TOKS / 8, 256>>>(out, b3);
    aux_kernel<<<1, 32>>>(out, out_size);
}